// round 12
// baseline (speedup 1.0000x reference)
#include <cuda_runtime.h>
#include <cuda_fp16.h>
#include <cstdint>
#include <math.h>

#define BATCH 8192
#define UNITS 1024
#define KTOT  2048
#define NCOL  4096

// ---------------- device scratch (allocation-free rule) ----------------
__device__ __half gA16[(size_t)BATCH * KTOT];   // [m][k], single-rounded
__device__ __half gB16[(size_t)NCOL * KTOT];    // [n][k] K-major (transposed), single-rounded

// ---------------- helpers ----------------
__device__ __forceinline__ uint32_t smem_to_u32(const void* p) {
    uint32_t a;
    asm("{ .reg .u64 t; cvta.to.shared.u64 t, %1; cvt.u32.u64 %0, t; }" : "=r"(a) : "l"(p));
    return a;
}
__device__ __forceinline__ void cp16(uint32_t dst, const void* src) {
    asm volatile("cp.async.cg.shared.global [%0], [%1], 16;" :: "r"(dst), "l"(src));
}
#define CP_COMMIT() asm volatile("cp.async.commit_group;" ::: "memory")

#define LDSM4(r, addr) \
    asm volatile("ldmatrix.sync.aligned.m8n8.x4.shared.b16 {%0,%1,%2,%3}, [%4];" \
        : "=r"((r)[0]), "=r"((r)[1]), "=r"((r)[2]), "=r"((r)[3]) : "r"(addr))

__device__ __forceinline__ void mma_f16(float* c, const uint32_t* a, uint32_t b0, uint32_t b1) {
    asm volatile("mma.sync.aligned.m16n8k16.row.col.f32.f16.f16.f32 "
        "{%0,%1,%2,%3}, {%4,%5,%6,%7}, {%8,%9}, {%0,%1,%2,%3};"
        : "+f"(c[0]), "+f"(c[1]), "+f"(c[2]), "+f"(c[3])
        : "r"(a[0]), "r"(a[1]), "r"(a[2]), "r"(a[3]), "r"(b0), "r"(b1));
}

// Fast transcendentals via MUFU (ex2/rcp approx: rel err ~2^-22, negligible vs 2.3e-4 budget).
__device__ __forceinline__ float fast_sig(float v) {
    float e, r;
    asm("ex2.approx.ftz.f32 %0, %1;" : "=f"(e) : "f"(-1.4426950408889634f * v));
    asm("rcp.approx.ftz.f32 %0, %1;" : "=f"(r) : "f"(1.0f + e));
    return r;
}
__device__ __forceinline__ float fast_tanh(float v) {
    float e, r;
    asm("ex2.approx.ftz.f32 %0, %1;" : "=f"(e) : "f"(2.8853900817779268f * v));  // e^{2v}
    asm("rcp.approx.ftz.f32 %0, %1;" : "=f"(r) : "f"(1.0f + e));
    return 1.0f - 2.0f * r;   // saturates correctly at +/-inf
}

// ---------------- fused conversion kernel (A blocks then B blocks) ----------------
#define NBLK_A 16384          // 8192*2048/4 elems4 / 256 threads
#define NBLK_B 8192           // (4096/32)*(2048/32)

__global__ __launch_bounds__(256)
void conv_kernel(const float4* __restrict__ x4, const float4* __restrict__ h4,
                 const float* __restrict__ W, const float* __restrict__ U)
{
    __shared__ float tile[32][33];
    if (blockIdx.x < NBLK_A) {
        size_t idx4 = (size_t)blockIdx.x * 256 + threadIdx.x;   // 0 .. 8192*512-1
        int m  = (int)(idx4 >> 9);
        int c4 = (int)(idx4 & 511);
        float4 v = (c4 < 256) ? x4[(size_t)m * 256 + c4]
                              : h4[(size_t)m * 256 + (c4 - 256)];
        __half2 p0, p1;
        p0.x = __float2half_rn(v.x); p0.y = __float2half_rn(v.y);
        p1.x = __float2half_rn(v.z); p1.y = __float2half_rn(v.w);
        ((__half2*)gA16)[idx4 * 2]     = p0;
        ((__half2*)gA16)[idx4 * 2 + 1] = p1;
    } else {
        const int bid = blockIdx.x - NBLK_A;
        const int n0 = (bid & 127) * 32, k0 = (bid >> 7) * 32;
        const int tx = threadIdx.x & 31, ty = threadIdx.x >> 5;
        #pragma unroll
        for (int i = 0; i < 4; i++) {
            int k = k0 + ty + i * 8;
            int n = n0 + tx;
            float v = (k < 1024) ? W[(size_t)k * 4096 + n] : U[(size_t)(k - 1024) * 4096 + n];
            tile[ty + i * 8][tx] = v;
        }
        __syncthreads();
        #pragma unroll
        for (int i = 0; i < 4; i++) {
            int nn = ty + i * 8;   // n within tile
            int kk = tx;           // k within tile
            gB16[(size_t)(n0 + nn) * KTOT + k0 + kk] = __float2half_rn(tile[kk][nn]);
        }
    }
}

// ---------------- fused MMA + LSTM-gate kernel ----------------
// CTA tile: 128 (M) x 128 (N) x BK=64. N cols interleaved: col = 4*u_local + gate (32 units/CTA).
// 256 threads = 8 warps: warp_m = warp&3 (32 M-rows), warp_n = warp>>2 (64 N-cols).
// Single-pass fp16, fp32 accumulate. 3-stage pipeline (32 KB stages), 32 iters,
// ONE __syncthreads per iteration. Rows 128 B; swizzle: chunk c at row r -> (c ^ (r&7)).
#define OFF_A 0
#define OFF_B 16384
#define STAGE_B 32768
#define NSTAGE 3
#define SMEM_TOTAL (NSTAGE * STAGE_B)   // 98304 (>= epilogue z 67584)
#define NITER 32                        // 2048 / 64
#define ZS4 33                          // z row stride in float4s (132 floats)

__global__ __launch_bounds__(256, 2)
void lstm_mma_kernel(const float* __restrict__ c_prev,
                     const float* __restrict__ bias,
                     const float* __restrict__ pf,
                     const float* __restrict__ pi,
                     const float* __restrict__ po,
                     float* __restrict__ out)
{
    extern __shared__ char smc[];
    const uint32_t sb = smem_to_u32(smc);
    const int tid  = threadIdx.x;
    const int lane = tid & 31;
    const int warp = tid >> 5;
    const int warp_m = warp & 3;        // 4 warps over M (32 rows each)
    const int warp_n = warp >> 2;       // 2 warps over N (64 cols each)
    const int bm = blockIdx.y * 128;
    const int u0 = blockIdx.x * 32;     // 32 units per CTA

    // ---- per-thread load slots: row = tid>>1 (0..127), half = tid&1 -> chunks 4h..4h+3 ----
    const int lr = tid >> 1, lh = tid & 1;
    uint32_t soff[4];
    #pragma unroll
    for (int j = 0; j < 4; j++) {
        const int c = lh * 4 + j;
        soff[j] = (uint32_t)(lr * 128 + ((c ^ (lr & 7)) << 4));
    }
    const uint32_t aoff = (uint32_t)(((size_t)(bm + lr) * KTOT) * 2 + lh * 64);
    const int ng = (lr & 3) * 1024 + u0 + (lr >> 2);   // gate-interleaved B row
    const uint32_t boff = (uint32_t)(((size_t)ng * KTOT) * 2 + lh * 64);
    const char* pA = (const char*)gA16;
    const char* pB = (const char*)gB16;

    // prologue: stages 0,1 hold k-chunks 0,1 (64 halfs = 128 B per iter)
    #pragma unroll
    for (int i = 0; i < 2; i++) {
        const uint32_t st = sb + i * STAGE_B;
        const uint32_t kb = (uint32_t)(i * 128);
        #pragma unroll
        for (int j = 0; j < 4; j++) {
            cp16(st + OFF_A + soff[j], pA + aoff + kb + j * 16);
            cp16(st + OFF_B + soff[j], pB + boff + kb + j * 16);
        }
        CP_COMMIT();
    }

    float acc[2][8][4];
    #pragma unroll
    for (int mt = 0; mt < 2; mt++)
        #pragma unroll
        for (int nt = 0; nt < 8; nt++)
            #pragma unroll
            for (int q = 0; q < 4; q++) acc[mt][nt][q] = 0.0f;

    // ldmatrix address components (fixed per thread, swizzle folded in; k-step = xor p<<5)
    const int a_row = warp_m * 32 + (lane & 15);                         // + mt*16 (keeps r&7)
    const int a_c0  = lane >> 4;
    const int b_row = warp_n * 64 + (lane & 7) + ((lane >> 4) & 1) * 8;  // + nt2*16 (keeps r&7)
    const int b_c0  = (lane >> 3) & 1;
    const uint32_t aob = (uint32_t)(a_row * 128 + ((a_c0 ^ (a_row & 7)) << 4));
    const uint32_t bob = (uint32_t)(b_row * 128 + ((b_c0 ^ (b_row & 7)) << 4));

    int stage = 0;
    for (int i = 0; i < NITER; i++) {
        if (i < NITER - 1) asm volatile("cp.async.wait_group 1;" ::: "memory");
        else               asm volatile("cp.async.wait_group 0;" ::: "memory");
        __syncthreads();   // single barrier: orders iter i-1 reads before stage reuse below

        // issue loads for chunk i+2 into stage (i+2)%3 (last read at iter i-1)
        if (i + 2 < NITER) {
            int ls = stage + 2; if (ls >= NSTAGE) ls -= NSTAGE;
            const uint32_t stn = sb + (uint32_t)ls * STAGE_B;
            const uint32_t kb  = (uint32_t)((i + 2) * 128);
            #pragma unroll
            for (int j = 0; j < 4; j++) {
                cp16(stn + OFF_A + soff[j], pA + aoff + kb + j * 16);
                cp16(stn + OFF_B + soff[j], pB + boff + kb + j * 16);
            }
            CP_COMMIT();
        }

        const uint32_t stA = sb + (uint32_t)stage * STAGE_B + OFF_A;
        const uint32_t stB = sb + (uint32_t)stage * STAGE_B + OFF_B;
        #pragma unroll
        for (int p = 0; p < 4; p++) {          // four k16-steps per BK=64
            const uint32_t kx = (uint32_t)(p << 5);
            uint32_t af[2][4], bf[4][4];
            #pragma unroll
            for (int mt = 0; mt < 2; mt++)
                LDSM4(af[mt], stA + ((aob ^ kx) + mt * 2048));
            #pragma unroll
            for (int nt2 = 0; nt2 < 4; nt2++)
                LDSM4(bf[nt2], stB + ((bob ^ kx) + nt2 * 2048));
            #pragma unroll
            for (int mt = 0; mt < 2; mt++)
                #pragma unroll
                for (int nt = 0; nt < 8; nt++)
                    mma_f16(acc[mt][nt], af[mt],
                            bf[nt >> 1][(nt & 1) * 2], bf[nt >> 1][(nt & 1) * 2 + 1]);
        }

        if (++stage == NSTAGE) stage = 0;
    }

    // ---- epilogue: stage z tile (128 x 128) to smem, then fused LSTM gates ----
    __syncthreads();
    float* z = (float*)smc;   // stride 132 floats -> 67584 B (fits in 98304)
    #pragma unroll
    for (int mt = 0; mt < 2; mt++) {
        const int row = warp_m * 32 + mt * 16 + (lane >> 2);
        #pragma unroll
        for (int nt = 0; nt < 8; nt++) {
            const int col = warp_n * 64 + nt * 8 + (lane & 3) * 2;
            z[row * (ZS4 * 4) + col]           = acc[mt][nt][0];
            z[row * (ZS4 * 4) + col + 1]       = acc[mt][nt][1];
            z[(row + 8) * (ZS4 * 4) + col]     = acc[mt][nt][2];
            z[(row + 8) * (ZS4 * 4) + col + 1] = acc[mt][nt][3];
        }
    }
    __syncthreads();

    const float4* zv4 = (const float4*)smc;
    #pragma unroll
    for (int pass = 0; pass < 16; pass++) {
        const int idx = pass * 256 + tid;     // 0 .. 4095
        const int m = idx >> 5;               // 0..127
        const int u = idx & 31;               // 0..31
        const int mg = bm + m;
        const int ug = u0 + u;
        const float4 zz = zv4[m * ZS4 + u];   // (zf, zi, zc, zo)
        const float zf = zz.x + bias[ug];
        const float zi = zz.y + bias[1024 + ug];
        const float zc = zz.z + bias[2048 + ug];
        const float zo = zz.w + bias[3072 + ug];
        const float cp = c_prev[(size_t)mg * UNITS + ug];
        const float f  = fast_sig(zf + pf[ug] * cp);
        const float ig = fast_sig(zi + pi[ug] * cp);
        const float ct = fast_tanh(zc);
        const float c  = f * cp + ig * ct;
        const float o  = fast_sig(zo + po[ug] * c);
        out[(size_t)mg * UNITS + ug] = o * fast_tanh(c);
        out[(size_t)BATCH * UNITS + (size_t)mg * UNITS + ug] = c;
    }
}

// ---------------- launch ----------------
extern "C" void kernel_launch(void* const* d_in, const int* in_sizes, int n_in,
                              void* d_out, int out_size)
{
    const float* x      = (const float*)d_in[0];
    const float* c_prev = (const float*)d_in[1];
    const float* h_prev = (const float*)d_in[2];
    const float* W      = (const float*)d_in[3];
    const float* U      = (const float*)d_in[4];
    const float* bias   = (const float*)d_in[5];
    const float* pf     = (const float*)d_in[6];
    const float* pi     = (const float*)d_in[7];
    const float* po     = (const float*)d_in[8];
    float* out = (float*)d_out;

    conv_kernel<<<NBLK_A + NBLK_B, 256>>>((const float4*)x, (const float4*)h_prev, W, U);

    cudaFuncSetAttribute(lstm_mma_kernel,
                         cudaFuncAttributeMaxDynamicSharedMemorySize, SMEM_TOTAL);
    lstm_mma_kernel<<<dim3(UNITS / 32, BATCH / 128), 256, SMEM_TOTAL>>>(
        c_prev, bias, pf, pi, po, out);
}

// round 13
// speedup vs baseline: 1.2240x; 1.2240x over previous
#include <cuda_runtime.h>
#include <cuda_fp16.h>
#include <cstdint>
#include <math.h>

#define BATCH 8192
#define UNITS 1024
#define KTOT  2048
#define NCOL  4096

// ---------------- device scratch (allocation-free rule) ----------------
__device__ __half gA16[(size_t)BATCH * KTOT];   // [m][k], single-rounded
__device__ __half gB16[(size_t)NCOL * KTOT];    // [n][k] K-major (transposed), single-rounded

// ---------------- helpers ----------------
__device__ __forceinline__ uint32_t smem_to_u32(const void* p) {
    uint32_t a;
    asm("{ .reg .u64 t; cvta.to.shared.u64 t, %1; cvt.u32.u64 %0, t; }" : "=r"(a) : "l"(p));
    return a;
}
__device__ __forceinline__ void cp16(uint32_t dst, const void* src) {
    asm volatile("cp.async.cg.shared.global [%0], [%1], 16;" :: "r"(dst), "l"(src));
}
#define CP_COMMIT() asm volatile("cp.async.commit_group;" ::: "memory")

#define LDSM4(r, addr) \
    asm volatile("ldmatrix.sync.aligned.m8n8.x4.shared.b16 {%0,%1,%2,%3}, [%4];" \
        : "=r"((r)[0]), "=r"((r)[1]), "=r"((r)[2]), "=r"((r)[3]) : "r"(addr))

__device__ __forceinline__ void mma_f16(float* c, const uint32_t* a, uint32_t b0, uint32_t b1) {
    asm volatile("mma.sync.aligned.m16n8k16.row.col.f32.f16.f16.f32 "
        "{%0,%1,%2,%3}, {%4,%5,%6,%7}, {%8,%9}, {%0,%1,%2,%3};"
        : "+f"(c[0]), "+f"(c[1]), "+f"(c[2]), "+f"(c[3])
        : "r"(a[0]), "r"(a[1]), "r"(a[2]), "r"(a[3]), "r"(b0), "r"(b1));
}

// Fast transcendentals via MUFU (ex2/rcp approx: rel err ~2^-22, negligible vs 2.3e-4 budget).
__device__ __forceinline__ float fast_sig(float v) {
    float e, r;
    asm("ex2.approx.ftz.f32 %0, %1;" : "=f"(e) : "f"(-1.4426950408889634f * v));
    asm("rcp.approx.ftz.f32 %0, %1;" : "=f"(r) : "f"(1.0f + e));
    return r;
}
__device__ __forceinline__ float fast_tanh(float v) {
    float e, r;
    asm("ex2.approx.ftz.f32 %0, %1;" : "=f"(e) : "f"(2.8853900817779268f * v));  // e^{2v}
    asm("rcp.approx.ftz.f32 %0, %1;" : "=f"(r) : "f"(1.0f + e));
    return 1.0f - 2.0f * r;   // saturates correctly at +/-inf
}

// ---------------- fused conversion kernel (A blocks then B blocks) ----------------
#define NBLK_A 16384          // 8192*2048/4 elems4 / 256 threads
#define NBLK_B 8192           // (4096/32)*(2048/32)

__global__ __launch_bounds__(256)
void conv_kernel(const float4* __restrict__ x4, const float4* __restrict__ h4,
                 const float* __restrict__ W, const float* __restrict__ U)
{
    __shared__ float tile[32][33];
    if (blockIdx.x < NBLK_A) {
        size_t idx4 = (size_t)blockIdx.x * 256 + threadIdx.x;   // 0 .. 8192*512-1
        int m  = (int)(idx4 >> 9);
        int c4 = (int)(idx4 & 511);
        float4 v = (c4 < 256) ? x4[(size_t)m * 256 + c4]
                              : h4[(size_t)m * 256 + (c4 - 256)];
        __half2 p0, p1;
        p0.x = __float2half_rn(v.x); p0.y = __float2half_rn(v.y);
        p1.x = __float2half_rn(v.z); p1.y = __float2half_rn(v.w);
        ((__half2*)gA16)[idx4 * 2]     = p0;
        ((__half2*)gA16)[idx4 * 2 + 1] = p1;
    } else {
        const int bid = blockIdx.x - NBLK_A;
        const int n0 = (bid & 127) * 32, k0 = (bid >> 7) * 32;
        const int tx = threadIdx.x & 31, ty = threadIdx.x >> 5;
        #pragma unroll
        for (int i = 0; i < 4; i++) {
            int k = k0 + ty + i * 8;
            int n = n0 + tx;
            float v = (k < 1024) ? W[(size_t)k * 4096 + n] : U[(size_t)(k - 1024) * 4096 + n];
            tile[ty + i * 8][tx] = v;
        }
        __syncthreads();
        #pragma unroll
        for (int i = 0; i < 4; i++) {
            int nn = ty + i * 8;   // n within tile
            int kk = tx;           // k within tile
            gB16[(size_t)(n0 + nn) * KTOT + k0 + kk] = __float2half_rn(tile[kk][nn]);
        }
    }
}

// ---------------- fused MMA + LSTM-gate kernel (proven R11 structure) ----------------
// CTA tile: 128 (M) x 128 (N) x BK=32. N cols interleaved: col = 4*u_local + gate (32 units/CTA).
// 256 threads = 8 warps: warp_m = warp&3 (32 M-rows), warp_n = warp>>2 (64 N-cols).
// Single-pass fp16, fp32 accumulate. 4-stage cp.async pipeline (prefetch distance 3,
// wait_group 2), ONE __syncthreads per iter. 64B rows; chunk c at row r -> (c ^ ((r>>1)&3)).
#define OFF_A 0
#define OFF_B 8192
#define STAGE_B 16384
#define NSTAGE 4
#define SMEM_TOTAL 67584                // max(4*16384=65536, epilogue z 67584)
#define NITER 64                        // 2048 / 32
#define ZS4 33                          // z row stride in float4s (132 floats)

__global__ __launch_bounds__(256, 2)
void lstm_mma_kernel(const float* __restrict__ c_prev,
                     const float* __restrict__ bias,
                     const float* __restrict__ pf,
                     const float* __restrict__ pi,
                     const float* __restrict__ po,
                     float* __restrict__ out)
{
    extern __shared__ char smc[];
    const uint32_t sb = smem_to_u32(smc);
    const int tid  = threadIdx.x;
    const int lane = tid & 31;
    const int warp = tid >> 5;
    const int warp_m = warp & 3;        // 4 warps over M (32 rows each)
    const int warp_n = warp >> 2;       // 2 warps over N (64 cols each)
    const int bm = blockIdx.y * 128;
    const int u0 = blockIdx.x * 32;     // 32 units per CTA

    // ---- per-thread load slots (2 per tile): row = tid>>2 (+64), chunk = tid&3 ----
    const int lr = tid >> 2, cch = tid & 3;
    uint32_t soff[2], aoff[2], boff[2];
    #pragma unroll
    for (int p = 0; p < 2; p++) {
        const int r = lr + p * 64;
        soff[p] = (uint32_t)(r * 64 + ((cch ^ ((r >> 1) & 3)) << 4));
        aoff[p] = (uint32_t)(((size_t)(bm + r) * KTOT + cch * 8) * 2);
        const int ng = (r & 3) * 1024 + u0 + (r >> 2);   // gate-interleaved B row
        boff[p] = (uint32_t)(((size_t)ng * KTOT + cch * 8) * 2);
    }
    const char* pA = (const char*)gA16;
    const char* pB = (const char*)gB16;

    // prologue: stages 0,1,2 hold k-chunks 0,1,2
    #pragma unroll
    for (int i = 0; i < 3; i++) {
        const uint32_t st = sb + i * STAGE_B;
        const uint32_t kb = (uint32_t)(i * 64);
        #pragma unroll
        for (int p = 0; p < 2; p++) {
            cp16(st + OFF_A + soff[p], pA + aoff[p] + kb);
            cp16(st + OFF_B + soff[p], pB + boff[p] + kb);
        }
        CP_COMMIT();
    }

    float acc[2][8][4];
    #pragma unroll
    for (int mt = 0; mt < 2; mt++)
        #pragma unroll
        for (int nt = 0; nt < 8; nt++)
            #pragma unroll
            for (int q = 0; q < 4; q++) acc[mt][nt][q] = 0.0f;

    // ldmatrix address components (fixed per thread, swizzle folded in)
    const int a_row = warp_m * 32 + (lane & 15);                         // + mt*16
    const int a_kc  = (lane >> 4);                                       // chunk += ks*2 (xor trick)
    const int b_row = warp_n * 64 + (lane & 7) + ((lane >> 4) & 1) * 8;  // + nt2*16
    const int b_kc  = ((lane >> 3) & 1);
    const uint32_t aob = (uint32_t)(a_row * 64 + ((a_kc ^ ((a_row >> 1) & 3)) << 4));
    const uint32_t bob = (uint32_t)(b_row * 64 + ((b_kc ^ ((b_row >> 1) & 3)) << 4));

    for (int i = 0; i < NITER; i++) {
        // chunk i must have landed: outstanding groups = chunks (i..min(i+2,NITER-1))
        if (i < NITER - 2)      asm volatile("cp.async.wait_group 2;" ::: "memory");
        else if (i < NITER - 1) asm volatile("cp.async.wait_group 1;" ::: "memory");
        else                    asm volatile("cp.async.wait_group 0;" ::: "memory");
        __syncthreads();   // single barrier: orders iter i-1 reads before stage reuse below

        // issue loads for chunk i+3 into stage (i+3)&3 (last read at iter i-1)
        if (i + 3 < NITER) {
            const uint32_t stn = sb + (uint32_t)((i + 3) & 3) * STAGE_B;
            const uint32_t kb  = (uint32_t)((i + 3) * 64);
            #pragma unroll
            for (int p = 0; p < 2; p++) {
                cp16(stn + OFF_A + soff[p], pA + aoff[p] + kb);
                cp16(stn + OFF_B + soff[p], pB + boff[p] + kb);
            }
            CP_COMMIT();
        }

        const uint32_t st = sb + (uint32_t)(i & 3) * STAGE_B;
        #pragma unroll
        for (int ks = 0; ks < 2; ks++) {
            const uint32_t kx = (uint32_t)(ks << 5);   // xor 32 bytes selects chunk+2
            uint32_t af[2][4], bf[4][4];
            #pragma unroll
            for (int mt = 0; mt < 2; mt++)
                LDSM4(af[mt], st + OFF_A + ((aob ^ kx) + mt * 1024));
            #pragma unroll
            for (int nt2 = 0; nt2 < 4; nt2++)
                LDSM4(bf[nt2], st + OFF_B + ((bob ^ kx) + nt2 * 1024));
            #pragma unroll
            for (int mt = 0; mt < 2; mt++)
                #pragma unroll
                for (int nt = 0; nt < 8; nt++)
                    mma_f16(acc[mt][nt], af[mt],
                            bf[nt >> 1][(nt & 1) * 2], bf[nt >> 1][(nt & 1) * 2 + 1]);
        }
    }

    // ---- epilogue: stage z tile (128 x 128) to smem, then fused LSTM gates ----
    __syncthreads();
    float* z = (float*)smc;   // stride 132 floats -> 67584 B
    #pragma unroll
    for (int mt = 0; mt < 2; mt++) {
        const int row = warp_m * 32 + mt * 16 + (lane >> 2);
        #pragma unroll
        for (int nt = 0; nt < 8; nt++) {
            const int col = warp_n * 64 + nt * 8 + (lane & 3) * 2;
            z[row * (ZS4 * 4) + col]           = acc[mt][nt][0];
            z[row * (ZS4 * 4) + col + 1]       = acc[mt][nt][1];
            z[(row + 8) * (ZS4 * 4) + col]     = acc[mt][nt][2];
            z[(row + 8) * (ZS4 * 4) + col + 1] = acc[mt][nt][3];
        }
    }
    __syncthreads();

    const float4* zv4 = (const float4*)smc;
    #pragma unroll
    for (int pass = 0; pass < 16; pass++) {
        const int idx = pass * 256 + tid;     // 0 .. 4095
        const int m = idx >> 5;               // 0..127
        const int u = idx & 31;               // 0..31
        const int mg = bm + m;
        const int ug = u0 + u;
        const float4 zz = zv4[m * ZS4 + u];   // (zf, zi, zc, zo)
        const float zf = zz.x + bias[ug];
        const float zi = zz.y + bias[1024 + ug];
        const float zc = zz.z + bias[2048 + ug];
        const float zo = zz.w + bias[3072 + ug];
        const float cp = c_prev[(size_t)mg * UNITS + ug];
        const float f  = fast_sig(zf + pf[ug] * cp);
        const float ig = fast_sig(zi + pi[ug] * cp);
        const float ct = fast_tanh(zc);
        const float c  = f * cp + ig * ct;
        const float o  = fast_sig(zo + po[ug] * c);
        out[(size_t)mg * UNITS + ug] = o * fast_tanh(c);
        out[(size_t)BATCH * UNITS + (size_t)mg * UNITS + ug] = c;
    }
}

// ---------------- launch ----------------
extern "C" void kernel_launch(void* const* d_in, const int* in_sizes, int n_in,
                              void* d_out, int out_size)
{
    const float* x      = (const float*)d_in[0];
    const float* c_prev = (const float*)d_in[1];
    const float* h_prev = (const float*)d_in[2];
    const float* W      = (const float*)d_in[3];
    const float* U      = (const float*)d_in[4];
    const float* bias   = (const float*)d_in[5];
    const float* pf     = (const float*)d_in[6];
    const float* pi     = (const float*)d_in[7];
    const float* po     = (const float*)d_in[8];
    float* out = (float*)d_out;

    conv_kernel<<<NBLK_A + NBLK_B, 256>>>((const float4*)x, (const float4*)h_prev, W, U);

    cudaFuncSetAttribute(lstm_mma_kernel,
                         cudaFuncAttributeMaxDynamicSharedMemorySize, SMEM_TOTAL);
    lstm_mma_kernel<<<dim3(UNITS / 32, BATCH / 128), 256, SMEM_TOTAL>>>(
        c_prev, bias, pf, pi, po, out);
}